// round 15
// baseline (speedup 1.0000x reference)
#include <cuda_runtime.h>
#include <cstdint>
#include <cstddef>

#define B_TOT 512
#define S_LEN 256
#define T_TAG 128
#define X_PAD (T_TAG + 2)
#define NB 2
#define NCTA (B_TOT / NB)      // 256 CTAs, 2 per SM
#define NTHREADS 256
#define LN2 0.6931471805599453f

__device__ float g_partial[NCTA];
__device__ int g_count = 0;

__device__ __forceinline__ float warp_sum(float v) {
#pragma unroll
    for (int o = 16; o > 0; o >>= 1)
        v += __shfl_xor_sync(0xffffffffu, v, o);
    return v;
}
__device__ __forceinline__ unsigned long long pack2(float lo, float hi) {
    unsigned long long r;
    asm("mov.b64 %0, {%1, %2};" : "=l"(r) : "f"(lo), "f"(hi));
    return r;
}
__device__ __forceinline__ void fma2(unsigned long long& acc, unsigned long long a,
                                     unsigned long long b) {
    asm("fma.rn.f32x2 %0, %1, %2, %0;" : "+l"(acc) : "l"(a), "l"(b));
}
__device__ __forceinline__ unsigned long long add2(unsigned long long a,
                                                   unsigned long long b) {
    unsigned long long r;
    asm("add.rn.f32x2 %0, %1, %2;" : "=l"(r) : "l"(a), "l"(b));
    return r;
}
__device__ __forceinline__ void unpack2(unsigned long long v, float& lo, float& hi) {
    asm("mov.b64 {%0, %1}, %2;" : "=f"(lo), "=f"(hi) : "l"(v));
}

__global__ __launch_bounds__(NTHREADS, 2) void crf_main(
    const float* __restrict__ emis,
    const void* __restrict__ tags_raw,
    const void* __restrict__ mask_raw,
    const float* __restrict__ trans,
    float* __restrict__ out)
{
    __shared__ __align__(16) float p_lin[NB][T_TAG];     // v (linear alpha), [batch][tag]
    __shared__ __align__(16) float2 xch[NB][4][X_PAD];   // [batch][chunk-pair][col]
    __shared__ float red_sh[8];                          // epilogue reductions only
    __shared__ float scr[NB];
    __shared__ float gred[8];
    __shared__ unsigned char msk[NB][S_LEN];
    __shared__ int is_last;

    const int tid  = threadIdx.x;
    const int lane = tid & 31;
    const int wid  = tid >> 5;
    // dot role: warp covers i in [16w,16w+16); half-warp ih covers 8 of them;
    // each lane covers 8 columns: colk = (lane&15) + 16k
    const int ih   = lane >> 4;
    const int lr   = lane & 15;
    const int i0   = wid * 16 + ih * 8;     // my 8 i's: i0..i0+7
    const int cp   = wid >> 1;              // chunk-pair plane
    const int par  = wid & 1;               // component within float2
    // reduce role: batch bb, column c
    const int bb   = tid >> 7;
    const int c    = tid & 127;
    const int b0   = blockIdx.x * NB;

    // ---- dtype probes (input-derived, deterministic) ----
    const int* t32 = (const int*)tags_raw;
    const int tags_is_i32 = __syncthreads_or(t32[2 * tid + 1] != 0);
    const int* m32 = (const int*)mask_raw;
    const unsigned char* m8 = (const unsigned char*)mask_raw;
    const bool mask_is_u8 = (m32[0] == 0x01010101);

#define MASK_AT(idx) (mask_is_u8 ? (m8[idx] != 0) : (m32[idx] != 0))
#define TAG_AT(idx)  (tags_is_i32 ? t32[idx] : t32[2 * (idx)])

    // ---- E packed along i: E2[ip][k] = (E[i0+2ip, colk], E[i0+2ip+1, colk]) ----
    unsigned long long E2[4][8];
#pragma unroll
    for (int ip = 0; ip < 4; ip++) {
#pragma unroll
        for (int kk = 0; kk < 8; kk++) {
            const int col = lr + 16 * kk;
            float elo = __expf(trans[(i0 + 2 * ip)     * T_TAG + col]);
            float ehi = __expf(trans[(i0 + 2 * ip + 1) * T_TAG + col]);
            E2[ip][kk] = pack2(elo, ehi);
        }
    }

    // ---- mask preload ----
    for (int idx = tid; idx < NB * S_LEN; idx += NTHREADS) {
        int nb = idx >> 8, tt = idx & 255;
        msk[nb][tt] = MASK_AT((unsigned)(b0 + nb) * S_LEN + tt) ? 1 : 0;
    }

    // 32-bit offsets: max index 2^24 < 2^31
    const unsigned eb = (unsigned)(b0 + bb) * (S_LEN * T_TAG);

    // ---- v0 = exp(em0), lsum = 0 ----
    float v = __expf(emis[eb + c]);
    float lsum = 0.f;
    p_lin[bb][c] = v;
    __syncthreads();   // covers p_lin, msk, probes

    // prefetch t=1
    float ex = __expf(emis[eb + T_TAG + c]);
    bool  k  = msk[bb][1] != 0;

    // ---- forward recursion (linear domain, v[1]-sampled rescale every 4th step) ----
#pragma unroll 2
    for (int t = 1; t < S_LEN; t++) {
        const bool resc = (t & 3) == 0;
        float s = 1.f, lg = 0.f;
        if (resc) {
            const float v1 = p_lin[bb][1];     // written last step, post-BAR2 safe
            s  = __fdividef(1.f, v1);
            lg = __log2f(v1);
        }
        const float ems = resc ? ex * s : ex;

        // prefetch t+1
        float exN = 0.f;
        bool  kN = false;
        if (t + 1 < S_LEN) {
            exN = __expf(emis[eb + (unsigned)(t + 1) * T_TAG + c]);
            kN = msk[bb][t + 1] != 0;
        }

        // ---- dot per batch: my 8 i's, 8 cols; fold+merge+store inside loop ----
#pragma unroll
        for (int b = 0; b < NB; b++) {
            // p loads: my 8 i's of batch b (half-warp-broadcast LDS.128 x2)
            ulonglong2 pv0 = *(const ulonglong2*)&p_lin[b][i0];
            ulonglong2 pv1 = *(const ulonglong2*)&p_lin[b][i0 + 4];
            unsigned long long acc[8];
#pragma unroll
            for (int kk = 0; kk < 8; kk++) acc[kk] = 0ull;
#pragma unroll
            for (int kk = 0; kk < 8; kk++) {
                fma2(acc[kk], E2[0][kk], pv0.x);
                fma2(acc[kk], E2[1][kk], pv0.y);
                fma2(acc[kk], E2[2][kk], pv1.x);
                fma2(acc[kk], E2[3][kk], pv1.y);
            }
            // fold even/odd i, merge half-warps, store (lanes<16)
#pragma unroll
            for (int kk = 0; kk < 8; kk++) {
                float lo, hi;
                unpack2(acc[kk], lo, hi);
                float Xh = lo + hi;                               // my 8-i partial
                Xh += __shfl_xor_sync(0xffffffffu, Xh, 16);       // merge ih halves
                if (lane < 16) {
                    const int col = lr + 16 * kk;
                    ((float*)&xch[b][cp][col])[par] = Xh;
                }
            }
        }
        __syncthreads();   // BAR1

        // ---- reduce 8 chunk partials (4 LDS.64 + add2 tree) — R13 verbatim ----
        const unsigned long long* xq = (const unsigned long long*)&xch[bb][0][c];
        unsigned long long u0 = add2(xq[0],         xq[X_PAD]);
        unsigned long long u1 = add2(xq[2 * X_PAD], xq[3 * X_PAD]);
        float xl, xh;
        unpack2(add2(u0, u1), xl, xh);
        const float X = xl + xh;

        if (k) { v = X * ems; lsum += resc ? lg : 0.f; }
        p_lin[bb][c] = v;

        ex = exN; k = kN;
        __syncthreads();   // BAR2: p visible to all dot warps
    }

    // ---- log_Z: ln Z = (log2(sum v) + lsum) * ln2 ----
    float su = warp_sum(v);
    if (lane == 0) red_sh[wid] = su;
    __syncthreads();
    if (c == 0) {   // tid 0 and 128
        const int rbase = bb * 4;
        scr[bb] = (__log2f(red_sh[rbase] + red_sh[rbase + 1] +
                           red_sh[rbase + 2] + red_sh[rbase + 3]) + lsum) * LN2;
    }

    // ---- gold: batch bb, 128 threads each ----
    {
        const unsigned tb  = (unsigned)(b0 + bb) * S_LEN;
        const unsigned ebn = tb * T_TAG;
        float gg = 0.f;
        for (int tt = c; tt < S_LEN; tt += 128) {
            int tg = TAG_AT(tb + tt);
            bool mk = msk[bb][tt] != 0;
            if (mk) gg += emis[ebn + (unsigned)tt * T_TAG + tg];
            if (tt + 1 < S_LEN) {
                if (mk && msk[bb][tt + 1]) gg += trans[tg * T_TAG + TAG_AT(tb + tt + 1)];
            }
        }
        gg = warp_sum(gg);
        if (lane == 0) gred[wid] = gg;
    }
    __syncthreads();   // scr + gred visible

    if (tid == 0) {
        float part = (scr[0] - (gred[0] + gred[1] + gred[2] + gred[3]))
                   + (scr[1] - (gred[4] + gred[5] + gred[6] + gred[7]));
        g_partial[blockIdx.x] = part;
        __threadfence();
        int old = atomicAdd(&g_count, 1);
        is_last = (old == NCTA - 1) ? 1 : 0;
    }
    __syncthreads();

    if (is_last) {
        __threadfence();
        float vv = (tid < NCTA) ? __ldcg(&g_partial[tid]) : 0.f;
        vv = warp_sum(vv);
        if (lane == 0) gred[wid] = vv;
        __syncthreads();
        if (tid == 0) {
            float tot = 0.f;
#pragma unroll
            for (int w = 0; w < 8; w++) tot += gred[w];
            out[0] = tot * (1.0f / (float)B_TOT);
            g_count = 0;   // reset for next graph replay
        }
    }
#undef MASK_AT
#undef TAG_AT
}

extern "C" void kernel_launch(void* const* d_in, const int* in_sizes, int n_in,
                              void* d_out, int out_size) {
    const float* emis  = (const float*)d_in[0];
    const void*  tags  = d_in[1];
    const void*  mask  = d_in[2];
    const float* trans = (const float*)d_in[3];
    float* out = (float*)d_out;

    crf_main<<<NCTA, NTHREADS>>>(emis, tags, mask, trans, out);
}